// round 1
// baseline (speedup 1.0000x reference)
#include <cuda_runtime.h>
#include <math.h>

#define NUM_LEVELS 16
#define TABLE_SIZE (1u << 19)
#define TSAMP 192

struct LevelParams {
    float scale[NUM_LEVELS];
    int   res[NUM_LEVELS];
    unsigned hashed_mask;
};

__device__ __forceinline__ float softplus10(float v) {
    // jax.nn.softplus(10x)/10 == logaddexp(10x, 0)/10
    float y = 10.0f * v;
    float sp = fmaxf(y, 0.0f) + log1pf(expf(-fabsf(y)));
    return sp * 0.1f;
}

__global__ __launch_bounds__(TSAMP, 2)
void nerf_fused(const float* __restrict__ x,
                const float4* __restrict__ emb,
                const float* __restrict__ W0,
                const float* __restrict__ b0,
                const float* __restrict__ W1,
                const float* __restrict__ b1,
                float* __restrict__ out,
                LevelParams lp)
{
    // W0 transposed: sWt[j][i] = W0[i][j]; pad 68 -> 272B rows (16B aligned,
    // write-phase conflicts only 4-way, read-phase is pure broadcast).
    __shared__ float sWt[64][68];
    __shared__ float sb0[64];
    __shared__ float sW1[64];

    const int tid = threadIdx.x;
    for (int e = tid; e < 4096; e += TSAMP) {
        int i = e >> 6, j = e & 63;
        sWt[j][i] = W0[e];             // coalesced global read
    }
    if (tid < 64) { sb0[tid] = b0[tid]; sW1[tid] = W1[tid]; }
    __syncthreads();

    const int ray = blockIdx.x;
    const float* xr = x + (size_t)ray * (TSAMP * 2);
    float ox = xr[0], oy = xr[1];
    float dxr = xr[(TSAMP - 1) * 2 + 0] - ox;
    float dyr = xr[(TSAMP - 1) * 2 + 1] - oy;
    float nrm = sqrtf(dxr * dxr + dyr * dyr);
    dxr = dxr / nrm;
    dyr = dyr / nrm;

    const float step = 2.0f / 191.0f;          // linspace(0, 2, 192) step
    float z = step * (float)tid;
    float px = fminf(fmaxf(ox + dxr * z, -1.0f), 1.0f);
    float py = fminf(fmaxf(oy + dyr * z, -1.0f), 1.0f);
    float ux = (px + 1.0f) * 0.5f;
    float uy = (py + 1.0f) * 0.5f;

    float feats[64];

    #pragma unroll
    for (int l = 0; l < NUM_LEVELS; ++l) {
        float s = lp.scale[l];
        float posx = ux * s + 0.5f;
        float posy = uy * s + 0.5f;
        float pfx = floorf(posx), pfy = floorf(posy);
        float frx = posx - pfx, fry = posy - pfy;
        int ix = (int)pfx, iy = (int)pfy;

        unsigned i00, i01, i10, i11;
        if (lp.hashed_mask & (1u << l)) {
            unsigned hy0 = (unsigned)iy * 2654435761u;
            unsigned hy1 = (unsigned)(iy + 1) * 2654435761u;
            unsigned hx0 = (unsigned)ix;
            unsigned hx1 = (unsigned)(ix + 1);
            i00 = (hx0 ^ hy0) & (TABLE_SIZE - 1u);
            i01 = (hx0 ^ hy1) & (TABLE_SIZE - 1u);
            i10 = (hx1 ^ hy0) & (TABLE_SIZE - 1u);
            i11 = (hx1 ^ hy1) & (TABLE_SIZE - 1u);
        } else {
            int res = lp.res[l];
            i00 = (unsigned)(iy * res + ix);
            i01 = (unsigned)((iy + 1) * res + ix);
            i10 = i00 + 1u;
            i11 = i01 + 1u;
        }

        const float4* tab = emb + (size_t)l * TABLE_SIZE;
        float4 c00 = __ldg(tab + i00);
        float4 c01 = __ldg(tab + i01);
        float4 c10 = __ldg(tab + i10);
        float4 c11 = __ldg(tab + i11);

        float w00 = (1.0f - frx) * (1.0f - fry);
        float w01 = (1.0f - frx) * fry;
        float w10 = frx * (1.0f - fry);
        float w11 = frx * fry;

        // reference corner order: (0,0),(0,1),(1,0),(1,1)
        feats[l * 4 + 0] = ((c00.x * w00 + c01.x * w01) + c10.x * w10) + c11.x * w11;
        feats[l * 4 + 1] = ((c00.y * w00 + c01.y * w01) + c10.y * w10) + c11.y * w11;
        feats[l * 4 + 2] = ((c00.z * w00 + c01.z * w01) + c10.z * w10) + c11.z * w11;
        feats[l * 4 + 3] = ((c00.w * w00 + c01.w * w01) + c10.w * w10) + c11.w * w11;
    }

    // h_j = softplus10(feats . W0[:,j] + b0[j]); sigma = softplus10(h . W1 + b1)
    float sig = __ldg(b1);
    for (int j = 0; j < 64; ++j) {
        const float4* wr = (const float4*)sWt[j];   // 272B-aligned row
        float a0 = sb0[j], a1 = 0.0f, a2 = 0.0f, a3 = 0.0f;
        #pragma unroll
        for (int k = 0; k < 16; k += 4) {
            float4 wA = wr[k + 0];
            a0 += feats[4*k + 0]*wA.x + feats[4*k + 1]*wA.y + feats[4*k + 2]*wA.z + feats[4*k + 3]*wA.w;
            float4 wB = wr[k + 1];
            a1 += feats[4*k + 4]*wB.x + feats[4*k + 5]*wB.y + feats[4*k + 6]*wB.z + feats[4*k + 7]*wB.w;
            float4 wC = wr[k + 2];
            a2 += feats[4*k + 8]*wC.x + feats[4*k + 9]*wC.y + feats[4*k +10]*wC.z + feats[4*k +11]*wC.w;
            float4 wD = wr[k + 3];
            a3 += feats[4*k +12]*wD.x + feats[4*k +13]*wD.y + feats[4*k +14]*wD.z + feats[4*k +15]*wD.w;
        }
        float hj = (a0 + a1) + (a2 + a3);
        float hact = softplus10(hj);
        sig += hact * sW1[j];
    }

    float sigma = softplus10(sig);
    float delta = (tid == 0) ? (1.0f / 192.0f) : (z - step * (float)(tid - 1));
    out[(size_t)ray * TSAMP + tid] = delta * sigma;
}

extern "C" void kernel_launch(void* const* d_in, const int* in_sizes, int n_in,
                              void* d_out, int out_size) {
    const float* x   = (const float*)d_in[0];   // [4,2048,192,2]
    const float* emb = (const float*)d_in[1];   // [16, 524288, 4]
    const float* W0  = (const float*)d_in[2];   // [64,64]
    const float* b0  = (const float*)d_in[3];   // [64]
    const float* W1  = (const float*)d_in[4];   // [64,1]
    const float* b1  = (const float*)d_in[5];   // [1]
    float* out = (float*)d_out;

    LevelParams lp;
    const double b = exp((log(2048.0) - log(2.0)) / 15.0);
    unsigned mask = 0;
    for (int l = 0; l < NUM_LEVELS; ++l) {
        double s = 2.0 * pow(b, (double)l) - 1.0;   // matches numpy SCALES
        lp.scale[l] = (float)s;
        int res = (int)ceil(s) + 1;
        lp.res[l] = res;
        if ((long long)res * (long long)res > (long long)TABLE_SIZE)
            mask |= (1u << l);
    }
    lp.hashed_mask = mask;

    int n_rays = (in_sizes[0] / (TSAMP * 2));   // 8192
    nerf_fused<<<n_rays, TSAMP>>>(x, (const float4*)emb, W0, b0, W1, b1, out, lp);
}

// round 2
// speedup vs baseline: 1.6481x; 1.6481x over previous
#include <cuda_runtime.h>
#include <math.h>

#define NUM_LEVELS 16
#define TABLE_SIZE (1u << 19)
#define TSAMP 192
#define PTS 128            // points per block
#define NTHREADS 256
#define FSTRIDE 68         // feats smem row stride (floats): (4r+c)%32 bijective
#define WSTRIDE 72         // W0 smem row stride (floats):   (8c+r)%32 bijective

struct LevelParams {
    float scale[NUM_LEVELS];
    int   res[NUM_LEVELS];
    unsigned hashed_mask;
};

__device__ __forceinline__ unsigned f2tf32(float v) {
    unsigned r;
    asm("cvt.rna.tf32.f32 %0, %1;" : "=r"(r) : "f"(v));
    return r;
}

__device__ __forceinline__ float softplus10(float v) {
    float y = 10.0f * v;
    float t = __expf(-fabsf(y));
    return (fmaxf(y, 0.0f) + __logf(1.0f + t)) * 0.1f;
}

#define MMA_TF32(C, A0, A1, A2, A3, B0, B1)                                    \
    asm volatile(                                                              \
        "mma.sync.aligned.m16n8k8.row.col.f32.tf32.tf32.f32 "                  \
        "{%0,%1,%2,%3}, {%4,%5,%6,%7}, {%8,%9}, {%0,%1,%2,%3};"                \
        : "+f"(C[0]), "+f"(C[1]), "+f"(C[2]), "+f"(C[3])                       \
        : "r"(A0), "r"(A1), "r"(A2), "r"(A3), "r"(B0), "r"(B1));

__global__ __launch_bounds__(NTHREADS, 2)
void nerf_fused(const float* __restrict__ x,
                const float4* __restrict__ emb,
                const float* __restrict__ W0,
                const float* __restrict__ b0,
                const float* __restrict__ W1,
                const float* __restrict__ b1,
                float* __restrict__ out,
                LevelParams lp)
{
    extern __shared__ float sm[];
    float* sF   = sm;                          // [PTS][FSTRIDE]
    float* sWhi = sF + PTS * FSTRIDE;          // [64][WSTRIDE]
    float* sWlo = sWhi + 64 * WSTRIDE;         // [64][WSTRIDE]
    float* sb0  = sWlo + 64 * WSTRIDE;         // [64]
    float* sW1  = sb0 + 64;                    // [64]
    float* sb1  = sW1 + 64;                    // [1]

    const int tid = threadIdx.x;

    // ---- W0 split into (tf32 hi, tf32 lo) in smem ----
    for (int e = tid; e < 4096; e += NTHREADS) {
        int k = e >> 6, n = e & 63;
        float w  = W0[e];
        float hi = __uint_as_float(f2tf32(w));
        float lo = w - hi;
        sWhi[k * WSTRIDE + n] = hi;
        sWlo[k * WSTRIDE + n] = __uint_as_float(f2tf32(lo));
    }
    if (tid < 64) { sb0[tid] = b0[tid]; sW1[tid] = W1[tid]; }
    if (tid == 0) { sb1[0] = b1[0]; }

    // ---- Phase 1: hash-grid gather; 2 threads per point (8 levels each) ----
    const int pt   = tid & (PTS - 1);
    const int half = tid >> 7;                  // levels [0..7] or [8..15]
    const int p    = blockIdx.x * PTS + pt;     // global point index
    const int ray  = p / TSAMP;
    const int t    = p - ray * TSAMP;

    const float2* xr = (const float2*)(x + (size_t)ray * (TSAMP * 2));
    float2 o  = xr[0];
    float2 en = xr[TSAMP - 1];
    float dxr = en.x - o.x, dyr = en.y - o.y;
    float nrm = sqrtf(dxr * dxr + dyr * dyr);
    dxr /= nrm; dyr /= nrm;

    const float step = 2.0f / 191.0f;
    float z  = step * (float)t;
    float ux = (fminf(fmaxf(o.x + dxr * z, -1.0f), 1.0f) + 1.0f) * 0.5f;
    float uy = (fminf(fmaxf(o.y + dyr * z, -1.0f), 1.0f) + 1.0f) * 0.5f;

    float* frow = sF + pt * FSTRIDE + half * 32;
    #pragma unroll
    for (int l2 = 0; l2 < 8; ++l2) {
        int l = (half << 3) + l2;
        float s = lp.scale[l];
        float posx = ux * s + 0.5f;
        float posy = uy * s + 0.5f;
        float pfx = floorf(posx), pfy = floorf(posy);
        float frx = posx - pfx,   fry = posy - pfy;
        int ix = (int)pfx, iy = (int)pfy;

        unsigned i00, i01, i10, i11;
        if (lp.hashed_mask & (1u << l)) {
            unsigned hy0 = (unsigned)iy * 2654435761u;
            unsigned hy1 = (unsigned)(iy + 1) * 2654435761u;
            i00 = ((unsigned)ix       ^ hy0) & (TABLE_SIZE - 1u);
            i01 = ((unsigned)ix       ^ hy1) & (TABLE_SIZE - 1u);
            i10 = ((unsigned)(ix + 1) ^ hy0) & (TABLE_SIZE - 1u);
            i11 = ((unsigned)(ix + 1) ^ hy1) & (TABLE_SIZE - 1u);
        } else {
            int res = lp.res[l];
            i00 = (unsigned)(iy * res + ix);
            i01 = i00 + (unsigned)res;
            i10 = i00 + 1u;
            i11 = i01 + 1u;
        }

        const float4* tab = emb + (size_t)l * TABLE_SIZE;
        float4 c00 = __ldg(tab + i00);
        float4 c01 = __ldg(tab + i01);
        float4 c10 = __ldg(tab + i10);
        float4 c11 = __ldg(tab + i11);

        float w00 = (1.0f - frx) * (1.0f - fry);
        float w01 = (1.0f - frx) * fry;
        float w10 = frx * (1.0f - fry);
        float w11 = frx * fry;

        float4 f4;
        f4.x = ((c00.x * w00 + c01.x * w01) + c10.x * w10) + c11.x * w11;
        f4.y = ((c00.y * w00 + c01.y * w01) + c10.y * w10) + c11.y * w11;
        f4.z = ((c00.z * w00 + c01.z * w01) + c10.z * w10) + c11.z * w11;
        f4.w = ((c00.w * w00 + c01.w * w01) + c10.w * w10) + c11.w * w11;
        *(float4*)(frow + l2 * 4) = f4;
    }

    __syncthreads();

    // ---- Phase 2: per-warp m16n8k8 tf32 GEMM (split-fp32, 3 passes) ----
    const int warp = tid >> 5;
    const int lane = tid & 31;
    const int r = lane >> 2;          // 0..7
    const int c = lane & 3;           // 0..3

    float C[8][4];
    #pragma unroll
    for (int nt = 0; nt < 8; ++nt) {
        C[nt][0] = 0.f; C[nt][1] = 0.f; C[nt][2] = 0.f; C[nt][3] = 0.f;
    }

    const float* Ab = sF + (warp * 16) * FSTRIDE;
    #pragma unroll
    for (int kk = 0; kk < 8; ++kk) {
        int kb = kk * 8;
        float a0f = Ab[r * FSTRIDE + kb + c];
        float a1f = Ab[(r + 8) * FSTRIDE + kb + c];
        float a2f = Ab[r * FSTRIDE + kb + c + 4];
        float a3f = Ab[(r + 8) * FSTRIDE + kb + c + 4];

        unsigned ah0 = f2tf32(a0f), ah1 = f2tf32(a1f),
                 ah2 = f2tf32(a2f), ah3 = f2tf32(a3f);
        unsigned al0 = f2tf32(a0f - __uint_as_float(ah0));
        unsigned al1 = f2tf32(a1f - __uint_as_float(ah1));
        unsigned al2 = f2tf32(a2f - __uint_as_float(ah2));
        unsigned al3 = f2tf32(a3f - __uint_as_float(ah3));

        int krow0 = (kb + c) * WSTRIDE;
        int krow4 = (kb + c + 4) * WSTRIDE;
        #pragma unroll
        for (int nt = 0; nt < 8; ++nt) {
            int n = nt * 8 + r;
            unsigned bh0 = __float_as_uint(sWhi[krow0 + n]);
            unsigned bh1 = __float_as_uint(sWhi[krow4 + n]);
            unsigned bl0 = __float_as_uint(sWlo[krow0 + n]);
            unsigned bl1 = __float_as_uint(sWlo[krow4 + n]);
            MMA_TF32(C[nt], ah0, ah1, ah2, ah3, bh0, bh1);
            MMA_TF32(C[nt], ah0, ah1, ah2, ah3, bl0, bl1);
            MMA_TF32(C[nt], al0, al1, al2, al3, bh0, bh1);
        }
    }

    // ---- Epilogue: softplus(h)·W1, reduce over cols, density out ----
    float sig0 = 0.f, sig1 = 0.f;
    #pragma unroll
    for (int nt = 0; nt < 8; ++nt) {
        int col0 = nt * 8 + 2 * c;
        int col1 = col0 + 1;
        float b0a = sb0[col0], b0b = sb0[col1];
        float w1a = sW1[col0], w1b = sW1[col1];
        sig0 += softplus10(C[nt][0] + b0a) * w1a;
        sig0 += softplus10(C[nt][1] + b0b) * w1b;
        sig1 += softplus10(C[nt][2] + b0a) * w1a;
        sig1 += softplus10(C[nt][3] + b0b) * w1b;
    }
    sig0 += __shfl_xor_sync(0xffffffffu, sig0, 1);
    sig0 += __shfl_xor_sync(0xffffffffu, sig0, 2);
    sig1 += __shfl_xor_sync(0xffffffffu, sig1, 1);
    sig1 += __shfl_xor_sync(0xffffffffu, sig1, 2);

    if (c == 0) {
        float b1v = sb1[0];
        #pragma unroll
        for (int hrow = 0; hrow < 2; ++hrow) {
            int local = warp * 16 + r + hrow * 8;
            int pp = blockIdx.x * PTS + local;
            int rr = pp / TSAMP;
            int tt = pp - rr * TSAMP;
            float sigv  = (hrow == 0) ? sig0 : sig1;
            float sigma = softplus10(b1v + sigv);
            float zt  = step * (float)tt;
            float zt1 = step * (float)(tt - 1);
            float delta = (tt == 0) ? (1.0f / 192.0f) : (zt - zt1);
            out[pp] = delta * sigma;
        }
    }
}

extern "C" void kernel_launch(void* const* d_in, const int* in_sizes, int n_in,
                              void* d_out, int out_size) {
    const float* x   = (const float*)d_in[0];   // [4,2048,192,2]
    const float* emb = (const float*)d_in[1];   // [16, 524288, 4]
    const float* W0  = (const float*)d_in[2];   // [64,64]
    const float* b0  = (const float*)d_in[3];   // [64]
    const float* W1  = (const float*)d_in[4];   // [64,1]
    const float* b1  = (const float*)d_in[5];   // [1]
    float* out = (float*)d_out;

    LevelParams lp;
    const double b = exp((log(2048.0) - log(2.0)) / 15.0);
    unsigned mask = 0;
    for (int l = 0; l < NUM_LEVELS; ++l) {
        double s = 2.0 * pow(b, (double)l) - 1.0;
        lp.scale[l] = (float)s;
        int res = (int)ceil(s) + 1;
        lp.res[l] = res;
        if ((long long)res * (long long)res > (long long)TABLE_SIZE)
            mask |= (1u << l);
    }
    lp.hashed_mask = mask;

    const int smem_bytes = (PTS * FSTRIDE + 2 * 64 * WSTRIDE + 129) * 4;
    static int attr_set = 0;
    if (!attr_set) {
        cudaFuncSetAttribute(nerf_fused,
                             cudaFuncAttributeMaxDynamicSharedMemorySize,
                             smem_bytes);
        attr_set = 1;
    }

    int n_points = in_sizes[0] / 2;             // 1,572,864
    int n_blocks = n_points / PTS;              // 12288
    nerf_fused<<<n_blocks, NTHREADS, smem_bytes>>>(x, (const float4*)emb,
                                                   W0, b0, W1, b1, out, lp);
}